// round 6
// baseline (speedup 1.0000x reference)
#include <cuda_runtime.h>
#include <cuda_fp16.h>
#include <cuda_fp8.h>
#include <cstdint>

#define KDIM 7168
#define NDIM 256
#define MTILE 128
#define NUMKB 56
#define NTHREADS 512

#define X16_SSTRIDE 16448
#define W16_SSTRIDE 32832
#define SO_X16 0
#define SO_W16 (2 * X16_SSTRIDE)             // 32896
#define SMEMT (SO_W16 + 2 * W16_SSTRIDE)     // 98560

#define SW(o) ((o) ^ ((((uint32_t)(o)) >> 3) & 0x70u))

__device__ __half   g_w16[NDIM * KDIM];   // ws-folded fp16 weight
__device__ int      g_flag;               // 0=fp32, 1=bf16, 2=fp8 bytes

// ---------- dtype sniffer ----------
__global__ void sniff_kernel(const uint32_t* __restrict__ wbits) {
    __shared__ int s_zero, s_big;
    if (threadIdx.x == 0) { s_zero = 0; s_big = 0; }
    __syncthreads();
    int zc = 0, bc = 0;
    for (int i = threadIdx.x; i < 4096; i += 256) {
        const uint32_t v = wbits[i];
        // e4m3 value stored as fp32 => mantissa bits [0:20) are all zero
        if ((v & 0x000FFFFFu) == 0) zc++;
        // bf16 interpretation of the two halves
        const float f0 = __uint_as_float(v << 16);
        const float f1 = __uint_as_float(v & 0xFFFF0000u);
        if (!(fabsf(f0) < 1.0f)) bc++;
        if (!(fabsf(f1) < 1.0f)) bc++;
    }
    atomicAdd(&s_zero, zc);
    atomicAdd(&s_big, bc);
    __syncthreads();
    if (threadIdx.x == 0)
        g_flag = (s_zero >= 4090) ? 0 : ((s_big == 0) ? 1 : 2);
}

// ---------- weight dequant: w16[n][k] = w[n][k] * ws[n/128][k/128] ----------
__global__ void wconv_kernel(const void* __restrict__ wraw,
                             const float* __restrict__ wscale) {
    const int flag = g_flag;
    const int base = (blockIdx.x * 256 + threadIdx.x) * 8;
    if (base >= NDIM * KDIM) return;
    const int n = base / KDIM;
    const int k = base % KDIM;     // 8-aligned, never crosses a row (7168 % 8 == 0)
    const float wsv = wscale[(n >> 7) * NUMKB + (k >> 7)];

    float f[8];
    if (flag == 0) {
        const float* p = (const float*)wraw + base;
        #pragma unroll
        for (int i = 0; i < 8; i++) f[i] = p[i];
    } else if (flag == 1) {
        const uint16_t* p = (const uint16_t*)wraw + base;
        #pragma unroll
        for (int i = 0; i < 8; i++) f[i] = __uint_as_float(((uint32_t)p[i]) << 16);
    } else {
        const uint8_t* p = (const uint8_t*)wraw + base;
        #pragma unroll
        for (int i = 0; i < 8; i += 2) {
            uint16_t pk = (uint16_t)(p[i] | (p[i + 1] << 8));
            __half2_raw hr = __nv_cvt_fp8x2_to_halfraw2((__nv_fp8x2_storage_t)pk, __NV_E4M3);
            float2 ff = __half22float2(*reinterpret_cast<__half2*>(&hr));
            f[i] = ff.x; f[i + 1] = ff.y;
        }
    }
    #pragma unroll
    for (int i = 0; i < 8; i += 2) {
        __half2 h = __floats2half2_rn(f[i] * wsv, f[i + 1] * wsv);
        *(__half2*)&g_w16[base + i] = h;
    }
}

// ---------- main fused kernel ----------
__device__ __forceinline__ uint32_t smem_u32(const void* p) {
    uint32_t a;
    asm("{ .reg .u64 t; cvta.to.shared.u64 t, %1; cvt.u32.u64 %0, t; }" : "=r"(a) : "l"(p));
    return a;
}

__device__ __forceinline__ void ldm_x4(uint32_t& r0, uint32_t& r1, uint32_t& r2, uint32_t& r3,
                                       uint32_t addr) {
    asm volatile("ldmatrix.sync.aligned.m8n8.x4.shared.b16 {%0,%1,%2,%3}, [%4];"
                 : "=r"(r0), "=r"(r1), "=r"(r2), "=r"(r3) : "r"(addr));
}

__device__ __forceinline__ void mma16816(float* d, uint32_t a0, uint32_t a1, uint32_t a2,
                                         uint32_t a3, uint32_t b0, uint32_t b1) {
    asm volatile("mma.sync.aligned.m16n8k16.row.col.f32.f16.f16.f32 "
                 "{%0,%1,%2,%3}, {%4,%5,%6,%7}, {%8,%9}, {%0,%1,%2,%3};"
                 : "+f"(d[0]), "+f"(d[1]), "+f"(d[2]), "+f"(d[3])
                 : "r"(a0), "r"(a1), "r"(a2), "r"(a3), "r"(b0), "r"(b1));
}

__device__ __forceinline__ uint32_t quant_pair(float a, float b, float sinv, float sact) {
    __nv_fp8x2_storage_t q = __nv_cvt_float2_to_fp8x2(make_float2(a * sinv, b * sinv),
                                                      __NV_SATFINITE, __NV_E4M3);
    __half2_raw hr = __nv_cvt_fp8x2_to_halfraw2(q, __NV_E4M3);
    float2 f = __half22float2(*reinterpret_cast<__half2*>(&hr));
    __half2 o = __floats2half2_rn(f.x * sact, f.y * sact);
    return *reinterpret_cast<uint32_t*>(&o);
}

__global__ void __launch_bounds__(NTHREADS, 1)
ds_gemm(const float* __restrict__ x, float* __restrict__ y)
{
    extern __shared__ char smem[];
    const uint32_t sb = smem_u32(smem);
    const int tid  = threadIdx.x;
    const int warp = tid >> 5;
    const int lane = tid & 31;
    const int m0   = blockIdx.x * MTILE;

    const int qr = tid >> 2;   // x quant: 4 threads per row
    const int qq = tid & 3;
    const int mw = warp & 3;   // warp grid 4m x 4n, warp tile 32x64
    const int nw = warp >> 2;
    const int wn = tid >> 1;   // w load: 2 threads per row
    const int wh = tid & 1;

    const int ri = lane & 7;
    const int qd = lane >> 3;
    const uint32_t a_row  = (uint32_t)(mw * 32 + ri + 8 * (qd & 1));
    const uint32_t a_colq = (uint32_t)(16 * (qd >> 1));
    const uint32_t b_rowc = (uint32_t)(nw * 64 + ri + 8 * (qd >> 1));
    const uint32_t b_colq = (uint32_t)(16 * (qd & 1));

    float acc[2][8][4];
    #pragma unroll
    for (int i = 0; i < 2; i++)
        #pragma unroll
        for (int j = 0; j < 8; j++)
            #pragma unroll
            for (int k = 0; k < 4; k++) acc[i][j][k] = 0.0f;

    const float* xptr = x + (size_t)(m0 + qr) * KDIM + qq * 32;
    float4 xr[8];
    #pragma unroll
    for (int j = 0; j < 8; j++) xr[j] = *(const float4*)(xptr + j * 4);

    const __half* wp = g_w16 + (size_t)wn * KDIM + wh * 64;
    const uint32_t xsts_base = sb + SO_X16 + (uint32_t)(qq >> 1) * X16_SSTRIDE;
    const uint32_t xsts_off0 = (uint32_t)(qr * 128 + (qq & 1) * 64);
    const uint32_t wsts_base = sb + SO_W16 + (uint32_t)wh * W16_SSTRIDE;

    for (int kb = 0; kb < NUMKB; kb++) {
        // ---- act quant (registers only) ----
        float amax = 0.0f;
        #pragma unroll
        for (int j = 0; j < 8; j++) {
            amax = fmaxf(amax, fmaxf(fmaxf(fabsf(xr[j].x), fabsf(xr[j].y)),
                                     fmaxf(fabsf(xr[j].z), fabsf(xr[j].w))));
        }
        amax = fmaxf(amax, __shfl_xor_sync(0xFFFFFFFFu, amax, 1));
        amax = fmaxf(amax, __shfl_xor_sync(0xFFFFFFFFu, amax, 2));
        const float am   = fmaxf(amax, 1e-8f);
        const float sact = am / 448.0f;
        const float sinv = 448.0f / am;

        uint32_t xh[16];
        #pragma unroll
        for (int j = 0; j < 8; j++) {
            xh[2 * j + 0] = quant_pair(xr[j].x, xr[j].y, sinv, sact);
            xh[2 * j + 1] = quant_pair(xr[j].z, xr[j].w, sinv, sact);
        }

        __syncthreads();  // previous block's mma reads finished

        #pragma unroll
        for (int i = 0; i < 4; i++) {
            const uint32_t a = xsts_base + SW(xsts_off0 + 16u * i);
            asm volatile("st.shared.v4.b32 [%0], {%1,%2,%3,%4};"
                         :: "r"(a), "r"(xh[4 * i]), "r"(xh[4 * i + 1]),
                            "r"(xh[4 * i + 2]), "r"(xh[4 * i + 3]) : "memory");
        }

        // ---- w16 tile: LDG (L2-resident) -> swizzled STS ----
        #pragma unroll
        for (int i = 0; i < 8; i++) {
            uint4 v = *(const uint4*)(wp + (size_t)kb * 128 + i * 8);
            const uint32_t a = wsts_base + SW((uint32_t)(wn * 128 + 16 * i));
            asm volatile("st.shared.v4.b32 [%0], {%1,%2,%3,%4};"
                         :: "r"(a), "r"(v.x), "r"(v.y), "r"(v.z), "r"(v.w) : "memory");
        }

        __syncthreads();  // tiles ready

        // ---- mma phase: 8 k-steps of m16n8k16 ----
        #pragma unroll
        for (int s = 0; s < 8; s++) {
            const uint32_t xb = sb + SO_X16 + (uint32_t)(s >> 2) * X16_SSTRIDE;
            const uint32_t wb = sb + SO_W16 + (uint32_t)(s >> 2) * W16_SSTRIDE;
            const uint32_t kbyte = 32u * (s & 3);

            uint32_t a0, a1, a2, a3, a4, a5, a6, a7;
            ldm_x4(a0, a1, a2, a3, xb + SW(a_row * 128 + kbyte + a_colq));
            ldm_x4(a4, a5, a6, a7, xb + SW((a_row + 16) * 128 + kbyte + a_colq));

            #pragma unroll
            for (int t = 0; t < 4; t++) {
                uint32_t b0, b1, b2, b3;
                ldm_x4(b0, b1, b2, b3, wb + SW((b_rowc + 16u * t) * 128 + kbyte + b_colq));
                mma16816(acc[0][2 * t],     a0, a1, a2, a3, b0, b1);
                mma16816(acc[0][2 * t + 1], a0, a1, a2, a3, b2, b3);
                mma16816(acc[1][2 * t],     a4, a5, a6, a7, b0, b1);
                mma16816(acc[1][2 * t + 1], a4, a5, a6, a7, b2, b3);
            }

            if (s == 3 && kb + 1 < NUMKB) {   // prefetch next x block mid-mma
                xptr += 128;
                #pragma unroll
                for (int j = 0; j < 8; j++) xr[j] = *(const float4*)(xptr + j * 4);
            }
        }
    }

    // ---- epilogue ----
    const int r0 = mw * 32 + (lane >> 2);
    const int c0 = nw * 64 + 2 * (lane & 3);
    #pragma unroll
    for (int mt = 0; mt < 2; mt++) {
        #pragma unroll
        for (int nt = 0; nt < 8; nt++) {
            const int row = m0 + r0 + 16 * mt;
            const int col = c0 + 8 * nt;
            *(float2*)&y[(size_t)row * NDIM + col] =
                make_float2(acc[mt][nt][0], acc[mt][nt][1]);
            *(float2*)&y[(size_t)(row + 8) * NDIM + col] =
                make_float2(acc[mt][nt][2], acc[mt][nt][3]);
        }
    }
}

extern "C" void kernel_launch(void* const* d_in, const int* in_sizes, int n_in,
                              void* d_out, int out_size) {
    // match inputs by element count (robust to ordering)
    const void*  w  = nullptr;
    const float* x  = nullptr;
    const float* ws = nullptr;
    long xcount = 0;
    for (int i = 0; i < n_in; i++) {
        if (in_sizes[i] > 4 * 1024 * 1024) { x = (const float*)d_in[i]; xcount = in_sizes[i]; }
        else if (in_sizes[i] > 1024)         w  = d_in[i];
        else                                 ws = (const float*)d_in[i];
    }
    float* y = (float*)d_out;
    const int M = (int)(xcount / KDIM);
    const int grid = M / MTILE;

    sniff_kernel<<<1, 256>>>((const uint32_t*)w);
    wconv_kernel<<<(NDIM * KDIM) / (256 * 8), 256>>>(w, ws);
    cudaFuncSetAttribute(ds_gemm, cudaFuncAttributeMaxDynamicSharedMemorySize, SMEMT);
    ds_gemm<<<grid, NTHREADS, SMEMT>>>(x, y);
}

// round 7
// speedup vs baseline: 1.1467x; 1.1467x over previous
#include <cuda_runtime.h>
#include <cuda_fp16.h>
#include <cuda_fp8.h>
#include <cstdint>

#define KDIM 7168
#define NDIM 256
#define MTILE 128
#define NUMKB 56
#define NTHREADS 512

#define X16_SSTRIDE 16448
#define W16_SSTRIDE 32832
#define STAGE (2 * X16_SSTRIDE + 2 * W16_SSTRIDE)   // 98560
#define SO_X(s) ((s) * STAGE)
#define SO_W(s) ((s) * STAGE + 2 * X16_SSTRIDE)
#define SMEMT (2 * STAGE)                           // 197120

#define SW(o) ((o) ^ ((((uint32_t)(o)) >> 3) & 0x70u))

__device__ __half g_w16[NDIM * KDIM];   // ws-folded fp16 weight

// ---------- weight dequant (with in-block dtype sniff) ----------
__global__ void wconv_kernel(const void* __restrict__ wraw,
                             const float* __restrict__ wscale) {
    __shared__ int s_zero, s_big;
    if (threadIdx.x == 0) { s_zero = 0; s_big = 0; }
    __syncthreads();
    const uint32_t* wb = (const uint32_t*)wraw;
    int zc = 0, bc = 0;
    for (int i = threadIdx.x; i < 4096; i += 256) {
        const uint32_t v = wb[i];
        if ((v & 0x000FFFFFu) == 0) zc++;   // fp32-holding-e4m3 signature
        const float f0 = __uint_as_float(v << 16);
        const float f1 = __uint_as_float(v & 0xFFFF0000u);
        if (!(fabsf(f0) < 1.0f)) bc++;
        if (!(fabsf(f1) < 1.0f)) bc++;
    }
    atomicAdd(&s_zero, zc);
    atomicAdd(&s_big, bc);
    __syncthreads();
    const int flag = (s_zero >= 4090) ? 0 : ((s_big == 0) ? 1 : 2);

    const int base = (blockIdx.x * 256 + threadIdx.x) * 8;
    if (base >= NDIM * KDIM) return;
    const int n = base / KDIM;
    const int k = base % KDIM;
    const float wsv = wscale[(n >> 7) * NUMKB + (k >> 7)];

    float f[8];
    if (flag == 0) {
        const float* p = (const float*)wraw + base;
        #pragma unroll
        for (int i = 0; i < 8; i++) f[i] = p[i];
    } else if (flag == 1) {
        const uint16_t* p = (const uint16_t*)wraw + base;
        #pragma unroll
        for (int i = 0; i < 8; i++) f[i] = __uint_as_float(((uint32_t)p[i]) << 16);
    } else {
        const uint8_t* p = (const uint8_t*)wraw + base;
        #pragma unroll
        for (int i = 0; i < 8; i += 2) {
            uint16_t pk = (uint16_t)(p[i] | (p[i + 1] << 8));
            __half2_raw hr = __nv_cvt_fp8x2_to_halfraw2((__nv_fp8x2_storage_t)pk, __NV_E4M3);
            float2 ff = __half22float2(*reinterpret_cast<__half2*>(&hr));
            f[i] = ff.x; f[i + 1] = ff.y;
        }
    }
    #pragma unroll
    for (int i = 0; i < 8; i += 2) {
        __half2 h = __floats2half2_rn(f[i] * wsv, f[i + 1] * wsv);
        *(__half2*)&g_w16[base + i] = h;
    }
}

// ---------- helpers ----------
__device__ __forceinline__ uint32_t smem_u32(const void* p) {
    uint32_t a;
    asm("{ .reg .u64 t; cvta.to.shared.u64 t, %1; cvt.u32.u64 %0, t; }" : "=r"(a) : "l"(p));
    return a;
}

__device__ __forceinline__ void ldm_x4(uint32_t& r0, uint32_t& r1, uint32_t& r2, uint32_t& r3,
                                       uint32_t addr) {
    asm volatile("ldmatrix.sync.aligned.m8n8.x4.shared.b16 {%0,%1,%2,%3}, [%4];"
                 : "=r"(r0), "=r"(r1), "=r"(r2), "=r"(r3) : "r"(addr));
}

__device__ __forceinline__ void mma16816(float* d, uint32_t a0, uint32_t a1, uint32_t a2,
                                         uint32_t a3, uint32_t b0, uint32_t b1) {
    asm("mma.sync.aligned.m16n8k16.row.col.f32.f16.f16.f32 "
        "{%0,%1,%2,%3}, {%4,%5,%6,%7}, {%8,%9}, {%0,%1,%2,%3};"
        : "+f"(d[0]), "+f"(d[1]), "+f"(d[2]), "+f"(d[3])
        : "r"(a0), "r"(a1), "r"(a2), "r"(a3), "r"(b0), "r"(b1));
}

__device__ __forceinline__ uint32_t quant_pair(float a, float b, float sinv, float sact) {
    __nv_fp8x2_storage_t q = __nv_cvt_float2_to_fp8x2(make_float2(a * sinv, b * sinv),
                                                      __NV_SATFINITE, __NV_E4M3);
    __half2_raw hr = __nv_cvt_fp8x2_to_halfraw2(q, __NV_E4M3);
    float2 f = __half22float2(*reinterpret_cast<__half2*>(&hr));
    __half2 o = __floats2half2_rn(f.x * sact, f.y * sact);
    return *reinterpret_cast<uint32_t*>(&o);
}

#define CPA16(dst, src) \
    asm volatile("cp.async.cg.shared.global [%0], [%1], 16;" :: "r"(dst), "l"(src) : "memory")

// ---------- main fused kernel ----------
__global__ void __launch_bounds__(NTHREADS, 1)
ds_gemm(const float* __restrict__ x, float* __restrict__ y)
{
    extern __shared__ char smem[];
    const uint32_t sb = smem_u32(smem);
    const int tid  = threadIdx.x;
    const int warp = tid >> 5;
    const int lane = tid & 31;
    const int m0   = blockIdx.x * MTILE;

    const int qr = tid >> 2;   // x quant: 4 threads per row
    const int qq = tid & 3;
    const int mw = warp & 3;   // warp grid 4m x 4n, warp tile 32x64
    const int nw = warp >> 2;
    const int wn = tid >> 1;   // w copy: 2 threads per row (64 halves each)
    const int wh = tid & 1;

    const int ri = lane & 7;
    const int qd = lane >> 3;
    const uint32_t a_row  = (uint32_t)(mw * 32 + ri + 8 * (qd & 1));
    const uint32_t a_colq = (uint32_t)(16 * (qd >> 1));
    const uint32_t b_rowc = (uint32_t)(nw * 64 + ri + 8 * (qd >> 1));
    const uint32_t b_colq = (uint32_t)(16 * (qd & 1));

    // per-thread fill addressing (stage-relative)
    const uint32_t xsts_sub  = (uint32_t)(qq >> 1) * X16_SSTRIDE;
    const uint32_t xsts_off0 = (uint32_t)(qr * 128 + (qq & 1) * 64);
    const uint32_t wdst_sub  = (uint32_t)wh * W16_SSTRIDE;
    const __half*  wsrc0     = g_w16 + (size_t)wn * KDIM + wh * 64;

    float acc[2][8][4];
    #pragma unroll
    for (int i = 0; i < 2; i++)
        #pragma unroll
        for (int j = 0; j < 8; j++)
            #pragma unroll
            for (int k = 0; k < 4; k++) acc[i][j][k] = 0.0f;

    const float* xptr = x + (size_t)(m0 + qr) * KDIM + qq * 32;
    float4 xr[8];
    #pragma unroll
    for (int j = 0; j < 8; j++) xr[j] = *(const float4*)(xptr + j * 4);

    // ---- prologue: fill stage 0 with kb=0 ----
    {
        // w via cp.async
        #pragma unroll
        for (int i = 0; i < 8; i++) {
            const uint32_t d = sb + SO_W(0) + wdst_sub + SW((uint32_t)(wn * 128 + 16 * i));
            CPA16(d, wsrc0 + i * 8);
        }
        asm volatile("cp.async.commit_group;" ::: "memory");

        // x quant -> STS
        float amax = 0.0f;
        #pragma unroll
        for (int j = 0; j < 8; j++)
            amax = fmaxf(amax, fmaxf(fmaxf(fabsf(xr[j].x), fabsf(xr[j].y)),
                                     fmaxf(fabsf(xr[j].z), fabsf(xr[j].w))));
        amax = fmaxf(amax, __shfl_xor_sync(0xFFFFFFFFu, amax, 1));
        amax = fmaxf(amax, __shfl_xor_sync(0xFFFFFFFFu, amax, 2));
        const float am = fmaxf(amax, 1e-8f);
        const float sact = am / 448.0f, sinv = 448.0f / am;
        uint32_t xh[16];
        #pragma unroll
        for (int j = 0; j < 8; j++) {
            xh[2 * j]     = quant_pair(xr[j].x, xr[j].y, sinv, sact);
            xh[2 * j + 1] = quant_pair(xr[j].z, xr[j].w, sinv, sact);
        }
        #pragma unroll
        for (int i = 0; i < 4; i++) {
            const uint32_t a = sb + SO_X(0) + xsts_sub + SW(xsts_off0 + 16u * i);
            asm volatile("st.shared.v4.b32 [%0], {%1,%2,%3,%4};"
                         :: "r"(a), "r"(xh[4 * i]), "r"(xh[4 * i + 1]),
                            "r"(xh[4 * i + 2]), "r"(xh[4 * i + 3]) : "memory");
        }
        asm volatile("cp.async.wait_group 0;" ::: "memory");
        __syncthreads();
    }

    for (int kb = 0; kb < NUMKB; kb++) {
        const int cur = kb & 1;
        const int nxt = cur ^ 1;
        const bool more = (kb + 1 < NUMKB);

        // ---- issue next tile's loads first (hidden under mma) ----
        if (more) {
            const __half* wsrc = wsrc0 + (size_t)(kb + 1) * 128;
            #pragma unroll
            for (int i = 0; i < 8; i++) {
                const uint32_t d = sb + SO_W(nxt) + wdst_sub + SW((uint32_t)(wn * 128 + 16 * i));
                CPA16(d, wsrc + i * 8);
            }
            asm volatile("cp.async.commit_group;" ::: "memory");
            xptr += 128;
            #pragma unroll
            for (int j = 0; j < 8; j++) xr[j] = *(const float4*)(xptr + j * 4);
        }

        // ---- mma phase on stage[cur]: 8 k-steps of m16n8k16 ----
        #pragma unroll
        for (int s = 0; s < 8; s++) {
            const uint32_t xb = sb + SO_X(cur) + (uint32_t)(s >> 2) * X16_SSTRIDE;
            const uint32_t wb = sb + SO_W(cur) + (uint32_t)(s >> 2) * W16_SSTRIDE;
            const uint32_t kbyte = 32u * (s & 3);

            uint32_t a0, a1, a2, a3, a4, a5, a6, a7;
            ldm_x4(a0, a1, a2, a3, xb + SW(a_row * 128 + kbyte + a_colq));
            ldm_x4(a4, a5, a6, a7, xb + SW((a_row + 16) * 128 + kbyte + a_colq));

            #pragma unroll
            for (int t = 0; t < 4; t++) {
                uint32_t b0, b1, b2, b3;
                ldm_x4(b0, b1, b2, b3, wb + SW((b_rowc + 16u * t) * 128 + kbyte + b_colq));
                mma16816(acc[0][2 * t],     a0, a1, a2, a3, b0, b1);
                mma16816(acc[0][2 * t + 1], a0, a1, a2, a3, b2, b3);
                mma16816(acc[1][2 * t],     a4, a5, a6, a7, b0, b1);
                mma16816(acc[1][2 * t + 1], a4, a5, a6, a7, b2, b3);
            }
        }

        // ---- quant next x and store into stage[nxt] ----
        if (more) {
            float amax = 0.0f;
            #pragma unroll
            for (int j = 0; j < 8; j++)
                amax = fmaxf(amax, fmaxf(fmaxf(fabsf(xr[j].x), fabsf(xr[j].y)),
                                         fmaxf(fabsf(xr[j].z), fabsf(xr[j].w))));
            amax = fmaxf(amax, __shfl_xor_sync(0xFFFFFFFFu, amax, 1));
            amax = fmaxf(amax, __shfl_xor_sync(0xFFFFFFFFu, amax, 2));
            const float am = fmaxf(amax, 1e-8f);
            const float sact = am / 448.0f, sinv = 448.0f / am;
            uint32_t xh[16];
            #pragma unroll
            for (int j = 0; j < 8; j++) {
                xh[2 * j]     = quant_pair(xr[j].x, xr[j].y, sinv, sact);
                xh[2 * j + 1] = quant_pair(xr[j].z, xr[j].w, sinv, sact);
            }
            #pragma unroll
            for (int i = 0; i < 4; i++) {
                const uint32_t a = sb + SO_X(nxt) + xsts_sub + SW(xsts_off0 + 16u * i);
                asm volatile("st.shared.v4.b32 [%0], {%1,%2,%3,%4};"
                             :: "r"(a), "r"(xh[4 * i]), "r"(xh[4 * i + 1]),
                                "r"(xh[4 * i + 2]), "r"(xh[4 * i + 3]) : "memory");
            }
            asm volatile("cp.async.wait_group 0;" ::: "memory");
            __syncthreads();
        }
    }

    // ---- epilogue ----
    const int r0 = mw * 32 + (lane >> 2);
    const int c0 = nw * 64 + 2 * (lane & 3);
    #pragma unroll
    for (int mt = 0; mt < 2; mt++) {
        #pragma unroll
        for (int nt = 0; nt < 8; nt++) {
            const int row = m0 + r0 + 16 * mt;
            const int col = c0 + 8 * nt;
            *(float2*)&y[(size_t)row * NDIM + col] =
                make_float2(acc[mt][nt][0], acc[mt][nt][1]);
            *(float2*)&y[(size_t)(row + 8) * NDIM + col] =
                make_float2(acc[mt][nt][2], acc[mt][nt][3]);
        }
    }
}

extern "C" void kernel_launch(void* const* d_in, const int* in_sizes, int n_in,
                              void* d_out, int out_size) {
    const void*  w  = nullptr;
    const float* x  = nullptr;
    const float* ws = nullptr;
    long xcount = 0;
    for (int i = 0; i < n_in; i++) {
        if (in_sizes[i] > 4 * 1024 * 1024) { x = (const float*)d_in[i]; xcount = in_sizes[i]; }
        else if (in_sizes[i] > 1024)         w  = d_in[i];
        else                                 ws = (const float*)d_in[i];
    }
    float* y = (float*)d_out;
    const int M = (int)(xcount / KDIM);
    const int grid = M / MTILE;

    wconv_kernel<<<(NDIM * KDIM) / (256 * 8), 256>>>(w, ws);
    cudaFuncSetAttribute(ds_gemm, cudaFuncAttributeMaxDynamicSharedMemorySize, SMEMT);
    ds_gemm<<<grid, NTHREADS, SMEMT>>>(x, y);
}